// round 1
// baseline (speedup 1.0000x reference)
#include <cuda_runtime.h>

#define BLK   256
#define DIMF  32
#define NHID  24
#define KM    31        // DIM-1 stacked layers

// smem weight-buffer layout (float offsets)
#define OFF_W1 0        // 31*? -> per-k: 24*32 = 768
#define OFF_B1 768      // 24
#define OFF_W2 792      // 576
#define OFF_B2 1368     // 24
#define OFF_W3 1392     // 576
#define OFF_B3 1968     // 24
#define OFF_W4 1992     // 48
#define OFF_B4 2040     // 2

__global__ __launch_bounds__(BLK, 2)
void slowmaf_kernel(const float* __restrict__ x,
                    const float* __restrict__ p0,
                    const float* __restrict__ W1, const float* __restrict__ b1,
                    const float* __restrict__ W2, const float* __restrict__ b2,
                    const float* __restrict__ W3, const float* __restrict__ b3,
                    const float* __restrict__ W4, const float* __restrict__ b4,
                    float* __restrict__ out)
{
    __shared__ __align__(16) float tile[BLK * 33];   // x staging, then z staging (row-private)
    __shared__ __align__(16) float wbuf[2048];       // per-k weights

    const int tid = threadIdx.x;
    const long b0 = (long)blockIdx.x * BLK;
    const long b  = b0 + tid;

    // ---- stage x coalesced, then pull this thread's row into registers ----
    {
        const float* xg = x + b0 * DIMF;
        for (int idx = tid; idx < BLK * DIMF; idx += BLK)
            tile[(idx >> 5) * 33 + (idx & 31)] = xg[idx];
    }
    __syncthreads();

    float xr[DIMF];
    #pragma unroll
    for (int j = 0; j < DIMF; ++j) xr[j] = tile[tid * 33 + j];
    // from here each thread only touches its own tile row -> no sync needed until final store

    // dim 0: LeafParam
    const float s0 = p0[0];
    const float t0 = p0[1];
    float s_sum = s0;
    tile[tid * 33 + 31] = xr[0] * expf(s0) + t0;      // z[:, 31] = vals[:, 0]

    float ha[NHID], hb[NHID];

    for (int k = 0; k < KM; ++k) {
        __syncthreads();   // all threads done reading wbuf from previous k
        // ---- cooperative load of layer-k weights into smem ----
        {
            const float* s1 = W1 + k * (NHID * DIMF);
            for (int i = tid; i < NHID * DIMF; i += BLK) wbuf[OFF_W1 + i] = s1[i];
            const float* s2 = W2 + k * (NHID * NHID);
            for (int i = tid; i < NHID * NHID; i += BLK) wbuf[OFF_W2 + i] = s2[i];
            const float* s3 = W3 + k * (NHID * NHID);
            for (int i = tid; i < NHID * NHID; i += BLK) wbuf[OFF_W3 + i] = s3[i];
            if (tid < NHID) {
                wbuf[OFF_B1 + tid] = b1[k * NHID + tid];
                wbuf[OFF_B2 + tid] = b2[k * NHID + tid];
                wbuf[OFF_B3 + tid] = b3[k * NHID + tid];
            } else if (tid < NHID + 48) {
                const int i = tid - NHID;
                wbuf[OFF_W4 + i] = W4[k * 48 + i];
            } else if (tid < NHID + 50) {
                const int i = tid - (NHID + 48);
                wbuf[OFF_B4 + i] = b4[k * 2 + i];
            }
        }
        __syncthreads();

        // ---- layer 1: (32 -> 24), causal: only cols 0..k are nonzero ----
        #pragma unroll
        for (int h = 0; h < NHID; ++h) ha[h] = wbuf[OFF_B1 + h];
        #pragma unroll
        for (int j4 = 0; j4 < DIMF / 4; ++j4) {
            if (4 * j4 > k) break;   // weights beyond col k are zero (pre-masked)
            const float x0 = xr[4 * j4 + 0], x1 = xr[4 * j4 + 1];
            const float x2 = xr[4 * j4 + 2], x3 = xr[4 * j4 + 3];
            #pragma unroll
            for (int h = 0; h < NHID; ++h) {
                const float4 w = *(const float4*)&wbuf[OFF_W1 + h * DIMF + 4 * j4];
                ha[h] += w.x * x0 + w.y * x1 + w.z * x2 + w.w * x3;
            }
        }
        #pragma unroll
        for (int h = 0; h < NHID; ++h) ha[h] = fmaxf(ha[h], 0.2f * ha[h]);

        // ---- layer 2: (24 -> 24) ----
        #pragma unroll
        for (int H = 0; H < NHID; ++H) {
            float acc = wbuf[OFF_B2 + H];
            #pragma unroll
            for (int h4 = 0; h4 < NHID / 4; ++h4) {
                const float4 w = *(const float4*)&wbuf[OFF_W2 + H * NHID + 4 * h4];
                acc += w.x * ha[4 * h4 + 0] + w.y * ha[4 * h4 + 1]
                     + w.z * ha[4 * h4 + 2] + w.w * ha[4 * h4 + 3];
            }
            hb[H] = fmaxf(acc, 0.2f * acc);
        }

        // ---- layer 3: (24 -> 24) ----
        #pragma unroll
        for (int H = 0; H < NHID; ++H) {
            float acc = wbuf[OFF_B3 + H];
            #pragma unroll
            for (int h4 = 0; h4 < NHID / 4; ++h4) {
                const float4 w = *(const float4*)&wbuf[OFF_W3 + H * NHID + 4 * h4];
                acc += w.x * hb[4 * h4 + 0] + w.y * hb[4 * h4 + 1]
                     + w.z * hb[4 * h4 + 2] + w.w * hb[4 * h4 + 3];
            }
            ha[H] = fmaxf(acc, 0.2f * acc);   // reuse ha as h3
        }

        // ---- layer 4: (24 -> 2) : (s, t) ----
        float s = wbuf[OFF_B4 + 0];
        float t = wbuf[OFF_B4 + 1];
        #pragma unroll
        for (int h4 = 0; h4 < NHID / 4; ++h4) {
            const float4 ws = *(const float4*)&wbuf[OFF_W4 + 0 * NHID + 4 * h4];
            const float4 wt = *(const float4*)&wbuf[OFF_W4 + 1 * NHID + 4 * h4];
            s += ws.x * ha[4 * h4 + 0] + ws.y * ha[4 * h4 + 1]
               + ws.z * ha[4 * h4 + 2] + ws.w * ha[4 * h4 + 3];
            t += wt.x * ha[4 * h4 + 0] + wt.y * ha[4 * h4 + 1]
               + wt.z * ha[4 * h4 + 2] + wt.w * ha[4 * h4 + 3];
        }
        s_sum += s;

        // select xr[k+1] without dynamic register indexing (avoid local-mem spill)
        float xk1 = 0.0f;
        #pragma unroll
        for (int j = 1; j < DIMF; ++j)
            if (k + 1 == j) xk1 = xr[j];

        // z[:, 31-(k+1)] = x[:, k+1] * exp(s) + t  (safe: col 30-k > k+1 was... row-private write)
        tile[tid * 33 + (30 - k)] = xk1 * expf(s) + t;
    }

    // log_det
    out[(long)65536 * DIMF + b] = s_sum;

    // ---- coalesced z store ----
    __syncthreads();
    {
        float* zg = out + b0 * DIMF;
        for (int idx = tid; idx < BLK * DIMF; idx += BLK)
            zg[idx] = tile[(idx >> 5) * 33 + (idx & 31)];
    }
}

extern "C" void kernel_launch(void* const* d_in, const int* in_sizes, int n_in,
                              void* d_out, int out_size)
{
    const float* x  = (const float*)d_in[0];
    const float* p0 = (const float*)d_in[1];
    const float* W1 = (const float*)d_in[2];
    const float* b1 = (const float*)d_in[3];
    const float* W2 = (const float*)d_in[4];
    const float* b2 = (const float*)d_in[5];
    const float* W3 = (const float*)d_in[6];
    const float* b3 = (const float*)d_in[7];
    const float* W4 = (const float*)d_in[8];
    const float* b4 = (const float*)d_in[9];
    float* out = (float*)d_out;

    const int B = in_sizes[0] / DIMF;   // 65536
    slowmaf_kernel<<<B / BLK, BLK>>>(x, p0, W1, b1, W2, b2, W3, b3, W4, b4, out);
}

// round 2
// speedup vs baseline: 1.7285x; 1.7285x over previous
#include <cuda_runtime.h>

#define BT   65536       // batch
#define KM   31          // DIM-1 stacked MLPs
#define BLK  128         // threads per main block; 2 rows/thread -> 256 rows/block

typedef unsigned long long ull;

// ---------------- scratch (device globals: allocation-free) ----------------
__device__ float g_xt[32 * BT];   // x transposed: g_xt[j*BT + b]
__device__ float g_s [KM * BT];   // per-k scale logits: g_s[k*BT + b]

// ---------------- f32x2 helpers ----------------
__device__ __forceinline__ ull ffma2(ull a, ull b, ull c) {
    ull d; asm("fma.rn.f32x2 %0, %1, %2, %3;" : "=l"(d) : "l"(a), "l"(b), "l"(c)); return d;
}
__device__ __forceinline__ ull dup2(float a) {
    ull d; asm("mov.b64 %0, {%1, %1};" : "=l"(d) : "f"(a)); return d;
}
__device__ __forceinline__ void unpack2(ull v, float& lo, float& hi) {
    asm("mov.b64 {%0, %1}, %2;" : "=f"(lo), "=f"(hi) : "l"(v));
}
__device__ __forceinline__ float lrelu(float v) { return fmaxf(v, 0.2f * v); }

// ---------------- smem layout (float offsets), all 16B aligned ----------------
#define XS   0            // x slice [j][r]: up to 32*256
#define W1T  8192         // W1 transposed [j=32][h=24]
#define B1   8960         // 24
#define W2T  8984         // W2 transposed [h=24][H=24]
#define B2   9560
#define W3T  9584
#define B3   10160
#define W4T  10184        // W4 transposed [h=24][o=2]  (s,t) pairs
#define B4   10232        // 2
#define SMF  10236

// 24->24 layer on a row-pair: inputs a0/a1 (24 scalars each, registers),
// weights transposed in smem (pairs (H,H+1) contiguous), outputs o0/o1.
__device__ __forceinline__ void layer24(const float* __restrict__ a0,
                                        const float* __restrict__ a1,
                                        const float* wt, const float* bias,
                                        float* __restrict__ o0,
                                        float* __restrict__ o1)
{
    ull acc0[12], acc1[12];
    const ull* bp = (const ull*)bias;
    #pragma unroll
    for (int p = 0; p < 12; ++p) { acc0[p] = bp[p]; acc1[p] = bp[p]; }
    #pragma unroll
    for (int h = 0; h < 24; ++h) {
        const ull pa = dup2(a0[h]);
        const ull pb = dup2(a1[h]);
        const ulonglong2* w = (const ulonglong2*)(wt + h * 24);
        #pragma unroll
        for (int q = 0; q < 6; ++q) {
            const ulonglong2 wq = w[q];
            acc0[2*q]   = ffma2(wq.x, pa, acc0[2*q]);
            acc1[2*q]   = ffma2(wq.x, pb, acc1[2*q]);
            acc0[2*q+1] = ffma2(wq.y, pa, acc0[2*q+1]);
            acc1[2*q+1] = ffma2(wq.y, pb, acc1[2*q+1]);
        }
    }
    #pragma unroll
    for (int p = 0; p < 12; ++p) {
        float lo, hi;
        unpack2(acc0[p], lo, hi); o0[2*p] = lrelu(lo); o0[2*p+1] = lrelu(hi);
        unpack2(acc1[p], lo, hi); o1[2*p] = lrelu(lo); o1[2*p+1] = lrelu(hi);
    }
}

// ---------------- kernel 1: transpose x into g_xt ----------------
__global__ void pack_x_kernel(const float* __restrict__ x)
{
    __shared__ float tile[256 * 33];
    const int tid  = threadIdx.x;
    const int base = blockIdx.x * 256;
    for (int idx = tid; idx < 256 * 32; idx += 256)
        tile[(idx >> 5) * 33 + (idx & 31)] = x[(size_t)base * 32 + idx];
    __syncthreads();
    for (int idx = tid; idx < 256 * 32; idx += 256) {
        const int j = idx >> 8, r = idx & 255;
        g_xt[j * BT + base + r] = tile[r * 33 + j];
    }
}

// ---------------- kernel 2: main — one (k, row-tile) per block ----------------
__global__ __launch_bounds__(BLK, 4)
void maf_main(const float* __restrict__ W1, const float* __restrict__ b1,
              const float* __restrict__ W2, const float* __restrict__ b2,
              const float* __restrict__ W3, const float* __restrict__ b3,
              const float* __restrict__ W4, const float* __restrict__ b4,
              float* __restrict__ out)
{
    __shared__ __align__(16) float sm[SMF];

    const int tid  = threadIdx.x;
    const int k    = blockIdx.y;
    const int base = blockIdx.x * 256;

    // ---- stage x slice (cols 0..k+1) and transposed weights ----
    {
        const int nx = (k + 2) * 256;
        for (int idx = tid; idx < nx; idx += BLK)
            sm[XS + idx] = g_xt[(idx >> 8) * BT + base + (idx & 255)];

        const float* gW1 = W1 + k * 768;
        for (int i = tid; i < 768; i += BLK) {
            const int h = i >> 5, j = i & 31;
            sm[W1T + j * 24 + h] = gW1[i];
        }
        const float* gW2 = W2 + k * 576;
        for (int i = tid; i < 576; i += BLK)
            sm[W2T + (i % 24) * 24 + (i / 24)] = gW2[i];
        const float* gW3 = W3 + k * 576;
        for (int i = tid; i < 576; i += BLK)
            sm[W3T + (i % 24) * 24 + (i / 24)] = gW3[i];
        const float* gW4 = W4 + k * 48;
        for (int i = tid; i < 48; i += BLK)
            sm[W4T + (i % 24) * 2 + (i / 24)] = gW4[i];
        if (tid < 24) {
            sm[B1 + tid] = b1[k * 24 + tid];
            sm[B2 + tid] = b2[k * 24 + tid];
            sm[B3 + tid] = b3[k * 24 + tid];
        }
        if (tid < 2) sm[B4 + tid] = b4[k * 2 + tid];
    }
    __syncthreads();

    // this thread's two rows: base+tid and base+tid+128
    float a0[24], a1[24], c0[24], c1[24];

    // ---- layer 1: (k+1) -> 24, inputs from smem x slice ----
    {
        ull acc0[12], acc1[12];
        const ull* bp = (const ull*)(sm + B1);
        #pragma unroll
        for (int p = 0; p < 12; ++p) { acc0[p] = bp[p]; acc1[p] = bp[p]; }
        for (int j = 0; j <= k; ++j) {
            const ull pa = dup2(sm[XS + j * 256 + tid]);
            const ull pb = dup2(sm[XS + j * 256 + tid + 128]);
            const ulonglong2* w = (const ulonglong2*)(sm + W1T + j * 24);
            #pragma unroll
            for (int q = 0; q < 6; ++q) {
                const ulonglong2 wq = w[q];
                acc0[2*q]   = ffma2(wq.x, pa, acc0[2*q]);
                acc1[2*q]   = ffma2(wq.x, pb, acc1[2*q]);
                acc0[2*q+1] = ffma2(wq.y, pa, acc0[2*q+1]);
                acc1[2*q+1] = ffma2(wq.y, pb, acc1[2*q+1]);
            }
        }
        #pragma unroll
        for (int p = 0; p < 12; ++p) {
            float lo, hi;
            unpack2(acc0[p], lo, hi); a0[2*p] = lrelu(lo); a0[2*p+1] = lrelu(hi);
            unpack2(acc1[p], lo, hi); a1[2*p] = lrelu(lo); a1[2*p+1] = lrelu(hi);
        }
    }

    // ---- layers 2 & 3 ----
    layer24(a0, a1, sm + W2T, sm + B2, c0, c1);
    layer24(c0, c1, sm + W3T, sm + B3, a0, a1);

    // ---- layer 4: 24 -> (s, t), natural (s,t) pairs ----
    ull st0 = *(const ull*)(sm + B4);
    ull st1 = st0;
    #pragma unroll
    for (int h = 0; h < 24; ++h) {
        const ull w  = ((const ull*)(sm + W4T))[h];
        st0 = ffma2(w, dup2(a0[h]), st0);
        st1 = ffma2(w, dup2(a1[h]), st1);
    }
    float s0, t0, s1, t1;
    unpack2(st0, s0, t0);
    unpack2(st1, s1, t1);

    // ---- outputs: z[:, 30-k] = x[:, k+1]*exp(s)+t ; s -> scratch ----
    const int r0 = base + tid;
    const int r1 = base + tid + 128;
    const float xk0 = sm[XS + (k + 1) * 256 + tid];
    const float xk1 = sm[XS + (k + 1) * 256 + tid + 128];
    out[(size_t)r0 * 32 + (30 - k)] = xk0 * expf(s0) + t0;
    out[(size_t)r1 * 32 + (30 - k)] = xk1 * expf(s1) + t1;
    g_s[k * BT + r0] = s0;
    g_s[k * BT + r1] = s1;
}

// ---------------- kernel 3: log_det reduce + dim-0 leaf ----------------
__global__ void reduce_kernel(const float* __restrict__ p0, float* __restrict__ out)
{
    const int b = blockIdx.x * 256 + threadIdx.x;
    const float s0 = p0[0];
    float sum = s0;
    #pragma unroll
    for (int k = 0; k < KM; ++k) sum += g_s[k * BT + b];
    out[(size_t)BT * 32 + b] = sum;                         // log_det
    out[(size_t)b * 32 + 31] = g_xt[b] * expf(s0) + p0[1];  // z col 31 = dim-0 leaf
}

extern "C" void kernel_launch(void* const* d_in, const int* in_sizes, int n_in,
                              void* d_out, int out_size)
{
    const float* x  = (const float*)d_in[0];
    const float* p0 = (const float*)d_in[1];
    const float* W1 = (const float*)d_in[2];
    const float* b1 = (const float*)d_in[3];
    const float* W2 = (const float*)d_in[4];
    const float* b2 = (const float*)d_in[5];
    const float* W3 = (const float*)d_in[6];
    const float* b3 = (const float*)d_in[7];
    const float* W4 = (const float*)d_in[8];
    const float* b4 = (const float*)d_in[9];
    float* out = (float*)d_out;

    pack_x_kernel<<<BT / 256, 256>>>(x);
    maf_main<<<dim3(BT / 256, KM), BLK>>>(W1, b1, W2, b2, W3, b3, W4, b4, out);
    reduce_kernel<<<BT / 256, 256>>>(p0, out);
}